// round 1
// baseline (speedup 1.0000x reference)
#include <cuda_runtime.h>
#include <cstdint>
#include <cstdio>

// Problem constants (shapes are fixed by the dataset)
#define DD 64
#define KK 2

// ---------------- scratch (static device globals; no allocation) ----------------
// tu: K x U x D   (U-part of u2e cell outputs)
// ti: K x I x D
// t : (U+I) x D   (u2i cell output)
// s : max-n x D   (shared "t+q" buffer, reused per cell; cells run serially)
__device__ float g_tu[2 * 100000 * 64];
__device__ float g_ti[2 * 100000 * 64];
__device__ float g_t [200000 * 64];
__device__ float g_s [200000 * 64];

// ---------------- f32x2 packed helpers (sm_103a) ----------------
__device__ __forceinline__ unsigned long long fma2(unsigned long long a,
                                                   unsigned long long b,
                                                   unsigned long long c) {
    unsigned long long d;
    asm("fma.rn.f32x2 %0, %1, %2, %3;" : "=l"(d) : "l"(a), "l"(b), "l"(c));
    return d;
}
__device__ __forceinline__ unsigned long long mul2(unsigned long long a,
                                                   unsigned long long b) {
    unsigned long long d;
    asm("mul.rn.f32x2 %0, %1, %2;" : "=l"(d) : "l"(a), "l"(b));
    return d;
}
__device__ __forceinline__ unsigned long long pk2(float x, float y) {
    unsigned long long r;
    asm("mov.b64 %0, {%1, %2};" : "=l"(r) : "f"(x), "f"(y));
    return r;
}
__device__ __forceinline__ float2 up2(unsigned long long v) {
    float2 r;
    asm("mov.b64 {%0, %1}, %2;" : "=f"(r.x), "=f"(r.y) : "l"(v));
    return r;
}
__device__ __forceinline__ void red4(float* p, float a, float b, float c, float d) {
    asm volatile("red.global.add.v4.f32 [%0], {%1, %2, %3, %4};"
                 :: "l"(p), "f"(a), "f"(b), "f"(c), "f"(d) : "memory");
}

// ---------------- fused dual GEMM: out = x@Tw+Tb ; s = out + (x*x)@Iw+Ib ----------------
// x is the virtual concat [xA (nA rows); xB (nB rows)], out is split the same way.
// Block: 256 threads, 64 rows per block, each warp owns 8 rows.
// Weights packed over k-pairs into smem for f32x2 FMA (2 fp32 MACs / instr).
__global__ __launch_bounds__(256) void gcn_gemm(
    const float* __restrict__ xA, int nA,
    const float* __restrict__ xB, int nB,
    const float* __restrict__ Tw, const float* __restrict__ Tb,
    const float* __restrict__ Iw, const float* __restrict__ Ib,
    float* __restrict__ outA, float* __restrict__ outB,
    float* __restrict__ sOut)
{
    const int n = nA + nB;
    // Single smem array, exactly 48KB: wT(4096f) | wI(4096f) | x(4096f)
    __shared__ __align__(16) float smem[12288];
    unsigned long long* sTwU = reinterpret_cast<unsigned long long*>(smem);
    unsigned long long* sIwU = reinterpret_cast<unsigned long long*>(smem + 4096);
    float* sX = smem + 8192;

    const int tid = threadIdx.x;

    // pack weights: sTwU[m*64 + j] = (Tw[2m][j], Tw[2m+1][j])
    for (int i = tid; i < 2048; i += 256) {
        int m = i >> 6, j = i & 63;
        sTwU[i] = pk2(Tw[(2 * m) * 64 + j], Tw[(2 * m + 1) * 64 + j]);
        sIwU[i] = pk2(Iw[(2 * m) * 64 + j], Iw[(2 * m + 1) * 64 + j]);
    }

    const int row0 = blockIdx.x * 64;
    // load x tile (64 rows x 64 floats), float4 per thread-iter
    for (int i = tid; i < 1024; i += 256) {
        int r = i >> 4, c4 = i & 15;
        int gr = row0 + r;
        float4 v = make_float4(0.f, 0.f, 0.f, 0.f);
        if (gr < n) {
            const float* src = (gr < nA) ? (xA + (size_t)gr * 64)
                                         : (xB + (size_t)(gr - nA) * 64);
            v = *reinterpret_cast<const float4*>(src + c4 * 4);
        }
        *reinterpret_cast<float4*>(sX + r * 64 + c4 * 4) = v;
    }
    __syncthreads();

    const int wid = tid >> 5;
    const int j = tid & 31;

    unsigned long long at0[8], at1[8], aq0[8], aq1[8];
#pragma unroll
    for (int r = 0; r < 8; ++r) { at0[r] = 0ULL; at1[r] = 0ULL; aq0[r] = 0ULL; aq1[r] = 0ULL; }

    const float* xbase = sX + (wid * 8) * 64;
#pragma unroll 4
    for (int m = 0; m < 32; ++m) {
        unsigned long long wtl = sTwU[(m << 6) + j];
        unsigned long long wth = sTwU[(m << 6) + j + 32];
        unsigned long long wil = sIwU[(m << 6) + j];
        unsigned long long wih = sIwU[(m << 6) + j + 32];
#pragma unroll
        for (int r = 0; r < 8; ++r) {
            unsigned long long xp =
                *reinterpret_cast<const unsigned long long*>(xbase + r * 64 + (m << 1));
            unsigned long long xx = mul2(xp, xp);
            at0[r] = fma2(xp, wtl, at0[r]);
            at1[r] = fma2(xp, wth, at1[r]);
            aq0[r] = fma2(xx, wil, aq0[r]);
            aq1[r] = fma2(xx, wih, aq1[r]);
        }
    }

    const float tb0 = Tb[j], tb1 = Tb[j + 32];
    const float sb0 = tb0 + Ib[j], sb1 = tb1 + Ib[j + 32];

#pragma unroll
    for (int r = 0; r < 8; ++r) {
        int gr = row0 + wid * 8 + r;
        if (gr >= n) break;
        float2 t0 = up2(at0[r]); float2 t1 = up2(at1[r]);
        float2 q0 = up2(aq0[r]); float2 q1 = up2(aq1[r]);
        float tr0 = t0.x + t0.y, tr1 = t1.x + t1.y;
        float qr0 = q0.x + q0.y, qr1 = q1.x + q1.y;
        float* op = (gr < nA) ? (outA + (size_t)gr * 64)
                              : (outB + (size_t)(gr - nA) * 64);
        op[j]      = tr0 + tb0;
        op[j + 32] = tr1 + tb1;
        sOut[(size_t)gr * 64 + j]      = tr0 + qr0 + sb0;
        sOut[(size_t)gr * 64 + j + 32] = tr1 + qr1 + sb1;
    }
}

// ---------------- edge scatter: out[row] += val * s[col]  (v4 f32 reductions) ----------------
// 16 lanes per edge, one float4 gather + one red.v4 per lane.
__global__ __launch_bounds__(256) void spmm_scatter(
    const int* __restrict__ rows, const int* __restrict__ cols,
    const float* __restrict__ vals, int nnz,
    const float* __restrict__ sIn,
    float* __restrict__ outA, int nA, float* __restrict__ outB)
{
    int t = blockIdx.x * 256 + threadIdx.x;
    int e = t >> 4;
    if (e >= nnz) return;
    int l = t & 15;
    int r = __ldg(rows + e);
    int c = __ldg(cols + e);
    float v = __ldg(vals + e);
    float4 sv = *reinterpret_cast<const float4*>(sIn + (size_t)c * 64 + l * 4);
    float* op = ((r < nA) ? (outA + (size_t)r * 64)
                          : (outB + (size_t)(r - nA) * 64)) + l * 4;
    red4(op, v * sv.x, v * sv.y, v * sv.z, v * sv.w);
}

// ---------------- relation attention over R=3 ----------------
// warp per node; lane = hidden unit h (H=32); w1 packed over k-pairs in registers.
__global__ __launch_bounds__(256) void rel_att_kernel(
    const float* __restrict__ z0, const float* __restrict__ z1,
    const float* __restrict__ z2,
    const float* __restrict__ w1, const float* __restrict__ b1,
    const float* __restrict__ w2, float* __restrict__ out, int n)
{
    __shared__ __align__(16) float zb[8][3][64];
    const int lane = threadIdx.x & 31;
    const int wid = threadIdx.x >> 5;

    unsigned long long w1p[32];
#pragma unroll
    for (int m = 0; m < 32; ++m)
        w1p[m] = pk2(w1[(2 * m) * 32 + lane], w1[(2 * m + 1) * 32 + lane]);
    const float b1v = b1[lane];
    const float w2v = w2[lane];

    const int warp0 = blockIdx.x * 8 + wid;
    const int nwarps = gridDim.x * 8;

    for (int node = warp0; node < n; node += nwarps) {
        size_t base = (size_t)node * 64;
        float za0 = z0[base + lane], za1 = z0[base + lane + 32];
        float zc0 = z1[base + lane], zc1 = z1[base + lane + 32];
        float zd0 = z2[base + lane], zd1 = z2[base + lane + 32];
        zb[wid][0][lane] = za0; zb[wid][0][lane + 32] = za1;
        zb[wid][1][lane] = zc0; zb[wid][1][lane + 32] = zc1;
        zb[wid][2][lane] = zd0; zb[wid][2][lane + 32] = zd1;
        __syncwarp();

        float wl[3];
#pragma unroll
        for (int jj = 0; jj < 3; ++jj) {
            const unsigned long long* zp =
                reinterpret_cast<const unsigned long long*>(zb[wid][jj]);
            unsigned long long acc = 0ULL;
#pragma unroll
            for (int m = 0; m < 32; ++m) acc = fma2(zp[m], w1p[m], acc);
            float2 a = up2(acc);
            float c = tanhf(a.x + a.y + b1v) * w2v;
#pragma unroll
            for (int o = 16; o; o >>= 1) c += __shfl_xor_sync(0xffffffffu, c, o);
            wl[jj] = c;
        }
        float mx = fmaxf(wl[0], fmaxf(wl[1], wl[2]));
        float e0 = __expf(wl[0] - mx), e1 = __expf(wl[1] - mx), e2 = __expf(wl[2] - mx);
        float inv = 1.0f / (e0 + e1 + e2);
        float beta0 = e0 * inv, beta1 = e1 * inv, beta2 = e2 * inv;
        out[base + lane]      = beta0 * za0 + beta1 * zc0 + beta2 * zd0;
        out[base + lane + 32] = beta0 * za1 + beta1 * zc1 + beta2 * zd1;
        __syncwarp();
    }
}

// ---------------- host launcher ----------------
extern "C" void kernel_launch(void* const* d_in, const int* in_sizes, int n_in,
                              void* d_out, int out_size)
{
    const int*   u2i_idx  = (const int*)  d_in[0];
    const float* u2i_val  = (const float*)d_in[1];
    const int*   u2e_idx  = (const int*)  d_in[2];
    const float* u2e_val  = (const float*)d_in[3];
    const int*   i2e_idx  = (const int*)  d_in[4];
    const float* i2e_val  = (const float*)d_in[5];
    const float* u_feat   = (const float*)d_in[6];
    const float* i_feat   = (const float*)d_in[7];
    const float* u2e_feat = (const float*)d_in[8];
    const float* i2e_feat = (const float*)d_in[9];
    const float* Tw_u2i = (const float*)d_in[10];
    const float* Tb_u2i = (const float*)d_in[11];
    const float* Iw_u2i = (const float*)d_in[12];
    const float* Ib_u2i = (const float*)d_in[13];
    const float* Tw_u2e = (const float*)d_in[14];
    const float* Tb_u2e = (const float*)d_in[15];
    const float* Iw_u2e = (const float*)d_in[16];
    const float* Ib_u2e = (const float*)d_in[17];
    const float* Tw_i2e = (const float*)d_in[18];
    const float* Tb_i2e = (const float*)d_in[19];
    const float* Iw_i2e = (const float*)d_in[20];
    const float* Ib_i2e = (const float*)d_in[21];
    const float* uatt_w1 = (const float*)d_in[22];
    const float* uatt_b1 = (const float*)d_in[23];
    const float* uatt_w2 = (const float*)d_in[24];
    const float* iatt_w1 = (const float*)d_in[25];
    const float* iatt_b1 = (const float*)d_in[26];
    const float* iatt_w2 = (const float*)d_in[27];

    const int U = in_sizes[6] / 64;
    const int I = in_sizes[7] / 64;
    const int E = in_sizes[8] / (2 * 64);
    const int NNZ_UI = in_sizes[1];
    const int NNZ_E  = in_sizes[3] / 2;

    float *tu, *ti, *t, *s;
    cudaGetSymbolAddress((void**)&tu, g_tu);
    cudaGetSymbolAddress((void**)&ti, g_ti);
    cudaGetSymbolAddress((void**)&t,  g_t);
    cudaGetSymbolAddress((void**)&s,  g_s);

    float* outp    = (float*)d_out;
    float* out_u   = outp;
    float* out_i   = outp + (size_t)U * 64;
    float* out_u2e = outp + (size_t)(U + I) * 64;
    float* out_i2e = out_u2e + (size_t)2 * E * 64;

    const dim3 blk(256);

    // u2e cells
    for (int k = 0; k < KK; ++k) {
        int n = U + E;
        gcn_gemm<<<(n + 63) / 64, blk>>>(
            u_feat, U, u2e_feat + (size_t)k * E * 64, E,
            Tw_u2e + k * 4096, Tb_u2e + k * 64,
            Iw_u2e + k * 4096, Ib_u2e + k * 64,
            tu + (size_t)k * U * 64, out_u2e + (size_t)k * E * 64, s);
        spmm_scatter<<<(NNZ_E * 16 + 255) / 256, blk>>>(
            u2e_idx + (size_t)k * 2 * NNZ_E,
            u2e_idx + (size_t)k * 2 * NNZ_E + NNZ_E,
            u2e_val + (size_t)k * NNZ_E, NNZ_E, s,
            tu + (size_t)k * U * 64, U, out_u2e + (size_t)k * E * 64);
    }
    // i2e cells
    for (int k = 0; k < KK; ++k) {
        int n = I + E;
        gcn_gemm<<<(n + 63) / 64, blk>>>(
            i_feat, I, i2e_feat + (size_t)k * E * 64, E,
            Tw_i2e + k * 4096, Tb_i2e + k * 64,
            Iw_i2e + k * 4096, Ib_i2e + k * 64,
            ti + (size_t)k * I * 64, out_i2e + (size_t)k * E * 64, s);
        spmm_scatter<<<(NNZ_E * 16 + 255) / 256, blk>>>(
            i2e_idx + (size_t)k * 2 * NNZ_E,
            i2e_idx + (size_t)k * 2 * NNZ_E + NNZ_E,
            i2e_val + (size_t)k * NNZ_E, NNZ_E, s,
            ti + (size_t)k * I * 64, I, out_i2e + (size_t)k * E * 64);
    }
    // u2i cell (output contiguous in g_t)
    {
        int n = U + I;
        gcn_gemm<<<(n + 63) / 64, blk>>>(
            u_feat, U, i_feat, I,
            Tw_u2i, Tb_u2i, Iw_u2i, Ib_u2i,
            t, t + (size_t)U * 64, s);
        // grid: NNZ_UI*16 threads
        long long tot = (long long)NNZ_UI * 16;
        spmm_scatter<<<(unsigned)((tot + 255) / 256), blk>>>(
            u2i_idx, u2i_idx + NNZ_UI, u2i_val, NNZ_UI, s,
            t, U + I, t);
    }
    // attention
    rel_att_kernel<<<1480, blk>>>(tu, tu + (size_t)U * 64, t,
                                  uatt_w1, uatt_b1, uatt_w2, out_u, U);
    rel_att_kernel<<<1480, blk>>>(ti, ti + (size_t)I * 64, t + (size_t)U * 64,
                                  iatt_w1, iatt_b1, iatt_w2, out_i, I);
}

// round 2
// speedup vs baseline: 1.3803x; 1.3803x over previous
#include <cuda_runtime.h>
#include <cstdint>
#include <cstdio>

// ---------------- scratch (static device globals; no allocation) ----------------
__device__ float g_tu[2 * 100000 * 64];
__device__ float g_ti[2 * 100000 * 64];
__device__ float g_t [200000 * 64];
__device__ float g_s [200000 * 64];
// packed tf32 weight fragments: 5 cells x [8kt][8nt][32lane] x float4(T.b0,T.b1,I.b0,I.b1)
__device__ float4 g_wp[5 * 2048];

// ---------------- helpers ----------------
__device__ __forceinline__ unsigned long long fma2(unsigned long long a,
                                                   unsigned long long b,
                                                   unsigned long long c) {
    unsigned long long d;
    asm("fma.rn.f32x2 %0, %1, %2, %3;" : "=l"(d) : "l"(a), "l"(b), "l"(c));
    return d;
}
__device__ __forceinline__ unsigned long long pk2(float x, float y) {
    unsigned long long r;
    asm("mov.b64 %0, {%1, %2};" : "=l"(r) : "f"(x), "f"(y));
    return r;
}
__device__ __forceinline__ float2 up2(unsigned long long v) {
    float2 r;
    asm("mov.b64 {%0, %1}, %2;" : "=f"(r.x), "=f"(r.y) : "l"(v));
    return r;
}
__device__ __forceinline__ void red4(float* p, float a, float b, float c, float d) {
    asm volatile("red.global.add.v4.f32 [%0], {%1, %2, %3, %4};"
                 :: "l"(p), "f"(a), "f"(b), "f"(c), "f"(d) : "memory");
}
__device__ __forceinline__ unsigned int tf32c(float f) {
    unsigned int r;
    asm("cvt.rna.tf32.f32 %0, %1;" : "=r"(r) : "f"(f));
    return r;
}
__device__ __forceinline__ void mma_tf32(float c[4],
                                         unsigned int a0, unsigned int a1,
                                         unsigned int a2, unsigned int a3,
                                         unsigned int b0, unsigned int b1) {
    asm("mma.sync.aligned.m16n8k8.row.col.f32.tf32.tf32.f32 "
        "{%0,%1,%2,%3}, {%4,%5,%6,%7}, {%8,%9}, {%0,%1,%2,%3};"
        : "+f"(c[0]), "+f"(c[1]), "+f"(c[2]), "+f"(c[3])
        : "r"(a0), "r"(a1), "r"(a2), "r"(a3), "r"(b0), "r"(b1));
}

// ---------------- weight fragment packer (once per launch) ----------------
// layout: [cell(5)][kt(8)][nt(8)][lane(32)] -> float4(Tb0, Tb1, Ib0, Ib1), tf32-converted
// frag b0 = w[kt*8 + lane%4][nt*8 + lane/4], b1 = w[kt*8 + lane%4 + 4][nt*8 + lane/4]
__global__ __launch_bounds__(256) void pack_weights(
    const float* tw0, const float* iw0, const float* tw1, const float* iw1,
    const float* tw2, const float* iw2, const float* tw3, const float* iw3,
    const float* tw4, const float* iw4, float4* wp)
{
    int idx = blockIdx.x * 256 + threadIdx.x;
    if (idx >= 5 * 2048) return;
    int c = idx >> 11;
    int kt = (idx >> 8) & 7;
    int nt = (idx >> 5) & 7;
    int l = idx & 31;
    const float* tw; const float* iw;
    switch (c) {
        case 0: tw = tw0; iw = iw0; break;
        case 1: tw = tw1; iw = iw1; break;
        case 2: tw = tw2; iw = iw2; break;
        case 3: tw = tw3; iw = iw3; break;
        default: tw = tw4; iw = iw4; break;
    }
    int k0 = kt * 8 + (l & 3);
    int n0 = nt * 8 + (l >> 2);
    float4 o;
    o.x = __uint_as_float(tf32c(tw[k0 * 64 + n0]));
    o.y = __uint_as_float(tf32c(tw[(k0 + 4) * 64 + n0]));
    o.z = __uint_as_float(tf32c(iw[k0 * 64 + n0]));
    o.w = __uint_as_float(tf32c(iw[(k0 + 4) * 64 + n0]));
    wp[idx] = o;
}

// ---------------- fused dual GEMM via tf32 tensor cores ----------------
// out = x@Tw + Tb ; s = out + (x*x)@Iw + Ib
// Block: 256 thr = 8 warps, 128 rows/block (16 rows per warp = one m16 tile).
__global__ __launch_bounds__(256) void gcn_gemm_tc(
    const float* __restrict__ xA, int nA,
    const float* __restrict__ xB, int nB,
    const float4* __restrict__ wp,
    const float* __restrict__ Tb, const float* __restrict__ Ib,
    float* __restrict__ outA, float* __restrict__ outB,
    float* __restrict__ sOut)
{
    __shared__ __align__(16) float sX[128 * 68];   // pad stride 68 for conflict-free frag reads
    const int n = nA + nB;
    const int row0 = blockIdx.x * 128;
    const int tid = threadIdx.x;

    // load x tile (128 rows x 64 floats)
    for (int i = tid; i < 128 * 16; i += 256) {
        int r = i >> 4, c4 = i & 15;
        int gr = row0 + r;
        float4 v = make_float4(0.f, 0.f, 0.f, 0.f);
        if (gr < n) {
            const float* src = (gr < nA) ? (xA + (size_t)gr * 64)
                                         : (xB + (size_t)(gr - nA) * 64);
            v = *reinterpret_cast<const float4*>(src + c4 * 4);
        }
        *reinterpret_cast<float4*>(sX + r * 68 + c4 * 4) = v;
    }
    __syncthreads();

    const int wid = tid >> 5;
    const int lane = tid & 31;
    const int g = lane >> 2;     // groupID (row within m16 tile)
    const int t4 = lane & 3;     // threadID in group

    const float* xr0 = sX + (wid * 16 + g) * 68;
    const float* xr1 = xr0 + 8 * 68;

    float cT[8][4], cQ[8][4];
#pragma unroll
    for (int ntt = 0; ntt < 8; ++ntt)
#pragma unroll
        for (int i = 0; i < 4; ++i) { cT[ntt][i] = 0.f; cQ[ntt][i] = 0.f; }

#pragma unroll
    for (int kt = 0; kt < 8; ++kt) {
        int c0 = kt * 8 + t4;
        float x0 = xr0[c0], x1 = xr1[c0], x2 = xr0[c0 + 4], x3 = xr1[c0 + 4];
        unsigned int a0 = tf32c(x0), a1 = tf32c(x1), a2 = tf32c(x2), a3 = tf32c(x3);
        unsigned int q0 = tf32c(x0 * x0), q1 = tf32c(x1 * x1);
        unsigned int q2 = tf32c(x2 * x2), q3 = tf32c(x3 * x3);
        const float4* wrow = wp + kt * 256 + lane;
#pragma unroll
        for (int nt = 0; nt < 8; ++nt) {
            float4 w = wrow[nt * 32];
            mma_tf32(cT[nt], a0, a1, a2, a3,
                     __float_as_uint(w.x), __float_as_uint(w.y));
            mma_tf32(cQ[nt], q0, q1, q2, q3,
                     __float_as_uint(w.z), __float_as_uint(w.w));
        }
    }

    // epilogue: row r0 = row0 + wid*16 + g (regs 0,1), row r1 = r0+8 (regs 2,3)
    const int r0 = row0 + wid * 16 + g;
    const int r1 = r0 + 8;
#pragma unroll
    for (int nt = 0; nt < 8; ++nt) {
        int col = nt * 8 + 2 * t4;
        float tbx = Tb[col], tby = Tb[col + 1];
        float ibx = Ib[col], iby = Ib[col + 1];
        if (r0 < n) {
            float tv0 = cT[nt][0] + tbx, tv1 = cT[nt][1] + tby;
            float sv0 = tv0 + cQ[nt][0] + ibx, sv1 = tv1 + cQ[nt][1] + iby;
            float* op = (r0 < nA) ? (outA + (size_t)r0 * 64)
                                  : (outB + (size_t)(r0 - nA) * 64);
            *reinterpret_cast<float2*>(op + col) = make_float2(tv0, tv1);
            *reinterpret_cast<float2*>(sOut + (size_t)r0 * 64 + col) = make_float2(sv0, sv1);
        }
        if (r1 < n) {
            float tv0 = cT[nt][2] + tbx, tv1 = cT[nt][3] + tby;
            float sv0 = tv0 + cQ[nt][2] + ibx, sv1 = tv1 + cQ[nt][3] + iby;
            float* op = (r1 < nA) ? (outA + (size_t)r1 * 64)
                                  : (outB + (size_t)(r1 - nA) * 64);
            *reinterpret_cast<float2*>(op + col) = make_float2(tv0, tv1);
            *reinterpret_cast<float2*>(sOut + (size_t)r1 * 64 + col) = make_float2(sv0, sv1);
        }
    }
}

// ---------------- edge scatter: out[row] += val * s[col] ----------------
// 16 lanes per edge, 2 edges per thread (MLP=2), coalesced gathers + red.v4.
__global__ __launch_bounds__(256) void spmm_scatter2(
    const int* __restrict__ rows, const int* __restrict__ cols,
    const float* __restrict__ vals, int nnz,
    const float* __restrict__ sIn,
    float* __restrict__ outA, int nA, float* __restrict__ outB)
{
    long long t = (long long)blockIdx.x * 256 + threadIdx.x;
    int l = (int)(t & 15);
    int e0 = (int)(t >> 4) * 2;
    if (e0 >= nnz) return;

    int r0 = __ldg(rows + e0);
    int c0 = __ldg(cols + e0);
    float v0 = __ldg(vals + e0);
    bool has1 = (e0 + 1) < nnz;
    int r1 = r0, c1 = c0;
    float v1 = 0.f;
    if (has1) {
        r1 = __ldg(rows + e0 + 1);
        c1 = __ldg(cols + e0 + 1);
        v1 = __ldg(vals + e0 + 1);
    }
    // both gathers issued before either red -> MLP 2
    float4 s0 = *reinterpret_cast<const float4*>(sIn + (size_t)c0 * 64 + l * 4);
    float4 s1 = *reinterpret_cast<const float4*>(sIn + (size_t)c1 * 64 + l * 4);

    float* p0 = ((r0 < nA) ? (outA + (size_t)r0 * 64)
                           : (outB + (size_t)(r0 - nA) * 64)) + l * 4;
    red4(p0, v0 * s0.x, v0 * s0.y, v0 * s0.z, v0 * s0.w);
    if (has1) {
        float* p1 = ((r1 < nA) ? (outA + (size_t)r1 * 64)
                               : (outB + (size_t)(r1 - nA) * 64)) + l * 4;
        red4(p1, v1 * s1.x, v1 * s1.y, v1 * s1.z, v1 * s1.w);
    }
}

// ---------------- relation attention over R=3 ----------------
__global__ __launch_bounds__(256) void rel_att_kernel(
    const float* __restrict__ z0, const float* __restrict__ z1,
    const float* __restrict__ z2,
    const float* __restrict__ w1, const float* __restrict__ b1,
    const float* __restrict__ w2, float* __restrict__ out, int n)
{
    __shared__ __align__(16) float zb[8][3][64];
    const int lane = threadIdx.x & 31;
    const int wid = threadIdx.x >> 5;

    unsigned long long w1p[32];
#pragma unroll
    for (int m = 0; m < 32; ++m)
        w1p[m] = pk2(w1[(2 * m) * 32 + lane], w1[(2 * m + 1) * 32 + lane]);
    const float b1v = b1[lane];
    const float w2v = w2[lane];

    const int warp0 = blockIdx.x * 8 + wid;
    const int nwarps = gridDim.x * 8;

    for (int node = warp0; node < n; node += nwarps) {
        size_t base = (size_t)node * 64;
        float za0 = z0[base + lane], za1 = z0[base + lane + 32];
        float zc0 = z1[base + lane], zc1 = z1[base + lane + 32];
        float zd0 = z2[base + lane], zd1 = z2[base + lane + 32];
        zb[wid][0][lane] = za0; zb[wid][0][lane + 32] = za1;
        zb[wid][1][lane] = zc0; zb[wid][1][lane + 32] = zc1;
        zb[wid][2][lane] = zd0; zb[wid][2][lane + 32] = zd1;
        __syncwarp();

        float wl[3];
#pragma unroll
        for (int jj = 0; jj < 3; ++jj) {
            const unsigned long long* zp =
                reinterpret_cast<const unsigned long long*>(zb[wid][jj]);
            unsigned long long acc = 0ULL;
#pragma unroll
            for (int m = 0; m < 32; ++m) acc = fma2(zp[m], w1p[m], acc);
            float2 a = up2(acc);
            float c = tanhf(a.x + a.y + b1v) * w2v;
#pragma unroll
            for (int o = 16; o; o >>= 1) c += __shfl_xor_sync(0xffffffffu, c, o);
            wl[jj] = c;
        }
        float mx = fmaxf(wl[0], fmaxf(wl[1], wl[2]));
        float e0 = __expf(wl[0] - mx), e1 = __expf(wl[1] - mx), e2 = __expf(wl[2] - mx);
        float inv = 1.0f / (e0 + e1 + e2);
        float beta0 = e0 * inv, beta1 = e1 * inv, beta2 = e2 * inv;
        out[base + lane]      = beta0 * za0 + beta1 * zc0 + beta2 * zd0;
        out[base + lane + 32] = beta0 * za1 + beta1 * zc1 + beta2 * zd1;
        __syncwarp();
    }
}

// ---------------- host launcher ----------------
extern "C" void kernel_launch(void* const* d_in, const int* in_sizes, int n_in,
                              void* d_out, int out_size)
{
    const int*   u2i_idx  = (const int*)  d_in[0];
    const float* u2i_val  = (const float*)d_in[1];
    const int*   u2e_idx  = (const int*)  d_in[2];
    const float* u2e_val  = (const float*)d_in[3];
    const int*   i2e_idx  = (const int*)  d_in[4];
    const float* i2e_val  = (const float*)d_in[5];
    const float* u_feat   = (const float*)d_in[6];
    const float* i_feat   = (const float*)d_in[7];
    const float* u2e_feat = (const float*)d_in[8];
    const float* i2e_feat = (const float*)d_in[9];
    const float* Tw_u2i = (const float*)d_in[10];
    const float* Tb_u2i = (const float*)d_in[11];
    const float* Iw_u2i = (const float*)d_in[12];
    const float* Ib_u2i = (const float*)d_in[13];
    const float* Tw_u2e = (const float*)d_in[14];
    const float* Tb_u2e = (const float*)d_in[15];
    const float* Iw_u2e = (const float*)d_in[16];
    const float* Ib_u2e = (const float*)d_in[17];
    const float* Tw_i2e = (const float*)d_in[18];
    const float* Tb_i2e = (const float*)d_in[19];
    const float* Iw_i2e = (const float*)d_in[20];
    const float* Ib_i2e = (const float*)d_in[21];
    const float* uatt_w1 = (const float*)d_in[22];
    const float* uatt_b1 = (const float*)d_in[23];
    const float* uatt_w2 = (const float*)d_in[24];
    const float* iatt_w1 = (const float*)d_in[25];
    const float* iatt_b1 = (const float*)d_in[26];
    const float* iatt_w2 = (const float*)d_in[27];

    const int U = in_sizes[6] / 64;
    const int I = in_sizes[7] / 64;
    const int E = in_sizes[8] / (2 * 64);
    const int NNZ_UI = in_sizes[1];
    const int NNZ_E  = in_sizes[3] / 2;

    float *tu, *ti, *t, *s;
    float4* wp4;
    cudaGetSymbolAddress((void**)&tu, g_tu);
    cudaGetSymbolAddress((void**)&ti, g_ti);
    cudaGetSymbolAddress((void**)&t,  g_t);
    cudaGetSymbolAddress((void**)&s,  g_s);
    cudaGetSymbolAddress((void**)&wp4, g_wp);

    float* outp    = (float*)d_out;
    float* out_u   = outp;
    float* out_i   = outp + (size_t)U * 64;
    float* out_u2e = outp + (size_t)(U + I) * 64;
    float* out_i2e = out_u2e + (size_t)2 * E * 64;

    const dim3 blk(256);

    // pack all 5 cells' weight fragments (cells 0,1 = u2e; 2,3 = i2e; 4 = u2i)
    pack_weights<<<40, blk>>>(
        Tw_u2e, Iw_u2e, Tw_u2e + 4096, Iw_u2e + 4096,
        Tw_i2e, Iw_i2e, Tw_i2e + 4096, Iw_i2e + 4096,
        Tw_u2i, Iw_u2i, wp4);

    // u2e cells
    for (int k = 0; k < 2; ++k) {
        int n = U + E;
        gcn_gemm_tc<<<(n + 127) / 128, blk>>>(
            u_feat, U, u2e_feat + (size_t)k * E * 64, E,
            wp4 + (size_t)k * 2048,
            Tb_u2e + k * 64, Ib_u2e + k * 64,
            tu + (size_t)k * U * 64, out_u2e + (size_t)k * E * 64, s);
        long long th = ((long long)NNZ_E + 1) / 2 * 16;
        spmm_scatter2<<<(unsigned)((th + 255) / 256), blk>>>(
            u2e_idx + (size_t)k * 2 * NNZ_E,
            u2e_idx + (size_t)k * 2 * NNZ_E + NNZ_E,
            u2e_val + (size_t)k * NNZ_E, NNZ_E, s,
            tu + (size_t)k * U * 64, U, out_u2e + (size_t)k * E * 64);
    }
    // i2e cells
    for (int k = 0; k < 2; ++k) {
        int n = I + E;
        gcn_gemm_tc<<<(n + 127) / 128, blk>>>(
            i_feat, I, i2e_feat + (size_t)k * E * 64, E,
            wp4 + (size_t)(2 + k) * 2048,
            Tb_i2e + k * 64, Ib_i2e + k * 64,
            ti + (size_t)k * I * 64, out_i2e + (size_t)k * E * 64, s);
        long long th = ((long long)NNZ_E + 1) / 2 * 16;
        spmm_scatter2<<<(unsigned)((th + 255) / 256), blk>>>(
            i2e_idx + (size_t)k * 2 * NNZ_E,
            i2e_idx + (size_t)k * 2 * NNZ_E + NNZ_E,
            i2e_val + (size_t)k * NNZ_E, NNZ_E, s,
            ti + (size_t)k * I * 64, I, out_i2e + (size_t)k * E * 64);
    }
    // u2i cell
    {
        int n = U + I;
        gcn_gemm_tc<<<(n + 127) / 128, blk>>>(
            u_feat, U, i_feat, I,
            wp4 + (size_t)4 * 2048,
            Tb_u2i, Ib_u2i,
            t, t + (size_t)U * 64, s);
        long long th = ((long long)NNZ_UI + 1) / 2 * 16;
        spmm_scatter2<<<(unsigned)((th + 255) / 256), blk>>>(
            u2i_idx, u2i_idx + NNZ_UI, u2i_val, NNZ_UI, s,
            t, U + I, t);
    }
    // attention
    rel_att_kernel<<<1480, blk>>>(tu, tu + (size_t)U * 64, t,
                                  uatt_w1, uatt_b1, uatt_w2, out_u, U);
    rel_att_kernel<<<1480, blk>>>(ti, ti + (size_t)I * 64, t + (size_t)U * 64,
                                  iatt_w1, iatt_b1, iatt_w2, out_i, I);
}

// round 3
// speedup vs baseline: 1.4878x; 1.0779x over previous
#include <cuda_runtime.h>
#include <cstdint>
#include <cstdio>

// ---------------- scratch (static device globals; no allocation) ----------------
__device__ float g_tu[2 * 100000 * 64];
__device__ float g_ti[2 * 100000 * 64];
__device__ float g_t [200000 * 64];
__device__ float g_s [800000 * 64];          // per-cell s buffers, cumulative rows
__device__ float2 g_wT[5 * 2048];            // packed tf32 T-weight frags
__device__ float2 g_wI[5 * 2048];            // packed tf32 I-weight frags

// ---------------- helpers ----------------
__device__ __forceinline__ unsigned long long fma2(unsigned long long a,
                                                   unsigned long long b,
                                                   unsigned long long c) {
    unsigned long long d;
    asm("fma.rn.f32x2 %0, %1, %2, %3;" : "=l"(d) : "l"(a), "l"(b), "l"(c));
    return d;
}
__device__ __forceinline__ unsigned long long pk2(float x, float y) {
    unsigned long long r;
    asm("mov.b64 %0, {%1, %2};" : "=l"(r) : "f"(x), "f"(y));
    return r;
}
__device__ __forceinline__ float2 up2(unsigned long long v) {
    float2 r;
    asm("mov.b64 {%0, %1}, %2;" : "=f"(r.x), "=f"(r.y) : "l"(v));
    return r;
}
__device__ __forceinline__ void red4(float* p, float a, float b, float c, float d) {
    asm volatile("red.global.add.v4.f32 [%0], {%1, %2, %3, %4};"
                 :: "l"(p), "f"(a), "f"(b), "f"(c), "f"(d) : "memory");
}
__device__ __forceinline__ unsigned int tf32c(float f) {
    unsigned int r;
    asm("cvt.rna.tf32.f32 %0, %1;" : "=r"(r) : "f"(f));
    return r;
}
__device__ __forceinline__ void mma_tf32(float c[4],
                                         unsigned int a0, unsigned int a1,
                                         unsigned int a2, unsigned int a3,
                                         unsigned int b0, unsigned int b1) {
    asm("mma.sync.aligned.m16n8k8.row.col.f32.tf32.tf32.f32 "
        "{%0,%1,%2,%3}, {%4,%5,%6,%7}, {%8,%9}, {%0,%1,%2,%3};"
        : "+f"(c[0]), "+f"(c[1]), "+f"(c[2]), "+f"(c[3])
        : "r"(a0), "r"(a1), "r"(a2), "r"(a3), "r"(b0), "r"(b1));
}

// ---------------- descriptor tables ----------------
struct GCell {
    const float* xA; const float* xB; int nA; int n;
    const float2* wT; const float2* wI;
    const float* Tb; const float* Ib;
    float* outA; float* outB; float* s;
};
struct GTab { int off[6]; GCell c[5]; };

struct SCell {
    const int* rows; const int* cols; const float* vals; int nnz;
    const float* sIn; float* outA; int nA; float* outB;
};
struct STab { int off[6]; SCell c[5]; };

// ---------------- weight fragment packer (once per launch) ----------------
// frag b0 = w[kt*8 + lane%4][nt*8 + lane/4], b1 = w[kt*8 + lane%4 + 4][...]
__global__ __launch_bounds__(256) void pack_weights(
    const float* tw0, const float* iw0, const float* tw1, const float* iw1,
    const float* tw2, const float* iw2, const float* tw3, const float* iw3,
    const float* tw4, const float* iw4, float2* wT, float2* wI)
{
    int idx = blockIdx.x * 256 + threadIdx.x;
    if (idx >= 5 * 2048) return;
    int c = idx >> 11;
    int kt = (idx >> 8) & 7;
    int nt = (idx >> 5) & 7;
    int l = idx & 31;
    const float* tw; const float* iw;
    switch (c) {
        case 0: tw = tw0; iw = iw0; break;
        case 1: tw = tw1; iw = iw1; break;
        case 2: tw = tw2; iw = iw2; break;
        case 3: tw = tw3; iw = iw3; break;
        default: tw = tw4; iw = iw4; break;
    }
    int k0 = kt * 8 + (l & 3);
    int n0 = nt * 8 + (l >> 2);
    float2 ot, oi;
    ot.x = __uint_as_float(tf32c(tw[k0 * 64 + n0]));
    ot.y = __uint_as_float(tf32c(tw[(k0 + 4) * 64 + n0]));
    oi.x = __uint_as_float(tf32c(iw[k0 * 64 + n0]));
    oi.y = __uint_as_float(tf32c(iw[(k0 + 4) * 64 + n0]));
    wT[idx] = ot;
    wI[idx] = oi;
}

// ---------------- fused dual GEMM (all 5 cells, one launch) ----------------
// Sequential T->Q phases share one accumulator: t = x@Tw+Tb written at midpoint,
// then Q-GEMM keeps accumulating -> s = t + x^2@Iw + Ib.
// 128 threads = 4 warps, 64 rows/block (16 rows per warp).
__global__ __launch_bounds__(128, 5) void gcn_gemm_all(GTab tab)
{
    __shared__ __align__(16) float sX[64 * 68];
    int b = blockIdx.x;
    int c = 0;
#pragma unroll
    for (int i = 1; i < 5; ++i) c += (b >= tab.off[i]);
    const GCell cl = tab.c[c];
    const int row0 = (b - tab.off[c]) * 64;
    const int tid = threadIdx.x;
    const int n = cl.n;

    // stage x tile (64 rows x 64 floats)
    for (int i = tid; i < 64 * 16; i += 128) {
        int r = i >> 4, c4 = i & 15;
        int gr = row0 + r;
        float4 v = make_float4(0.f, 0.f, 0.f, 0.f);
        if (gr < n) {
            const float* src = (gr < cl.nA) ? (cl.xA + (size_t)gr * 64)
                                            : (cl.xB + (size_t)(gr - cl.nA) * 64);
            v = *reinterpret_cast<const float4*>(src + c4 * 4);
        }
        *reinterpret_cast<float4*>(sX + r * 68 + c4 * 4) = v;
    }
    __syncthreads();

    const int wid = tid >> 5;
    const int lane = tid & 31;
    const int g = lane >> 2;
    const int t4 = lane & 3;
    const float* xr0 = sX + (wid * 16 + g) * 68;
    const float* xr1 = xr0 + 8 * 68;

    // x fragments in registers (raw fp32; squared on the fly for Q phase)
    float xf0[8], xf1[8], xf2[8], xf3[8];
#pragma unroll
    for (int kt = 0; kt < 8; ++kt) {
        int c0 = kt * 8 + t4;
        xf0[kt] = xr0[c0];
        xf1[kt] = xr1[c0];
        xf2[kt] = xr0[c0 + 4];
        xf3[kt] = xr1[c0 + 4];
    }

    float acc[8][4];
#pragma unroll
    for (int nt = 0; nt < 8; ++nt)
#pragma unroll
        for (int i = 0; i < 4; ++i) acc[nt][i] = 0.f;

    // ---- T phase ----
#pragma unroll
    for (int kt = 0; kt < 8; ++kt) {
        unsigned int a0 = tf32c(xf0[kt]), a1 = tf32c(xf1[kt]);
        unsigned int a2 = tf32c(xf2[kt]), a3 = tf32c(xf3[kt]);
        const float2* wr = cl.wT + kt * 256 + lane;
#pragma unroll
        for (int nt = 0; nt < 8; ++nt) {
            float2 w = wr[nt * 32];
            mma_tf32(acc[nt], a0, a1, a2, a3,
                     __float_as_uint(w.x), __float_as_uint(w.y));
        }
    }

    const int r0 = row0 + wid * 16 + g;
    const int r1 = r0 + 8;
    float* op0 = nullptr; float* op1 = nullptr;
    if (r0 < n) op0 = (r0 < cl.nA) ? (cl.outA + (size_t)r0 * 64)
                                   : (cl.outB + (size_t)(r0 - cl.nA) * 64);
    if (r1 < n) op1 = (r1 < cl.nA) ? (cl.outA + (size_t)r1 * 64)
                                   : (cl.outB + (size_t)(r1 - cl.nA) * 64);

    // midpoint epilogue: write t = acc + Tb
#pragma unroll
    for (int nt = 0; nt < 8; ++nt) {
        int col = nt * 8 + 2 * t4;
        float tbx = cl.Tb[col], tby = cl.Tb[col + 1];
        if (op0) *reinterpret_cast<float2*>(op0 + col) =
            make_float2(acc[nt][0] + tbx, acc[nt][1] + tby);
        if (op1) *reinterpret_cast<float2*>(op1 + col) =
            make_float2(acc[nt][2] + tbx, acc[nt][3] + tby);
    }

    // ---- Q phase (accumulates on top of T) ----
#pragma unroll
    for (int kt = 0; kt < 8; ++kt) {
        unsigned int q0 = tf32c(xf0[kt] * xf0[kt]), q1 = tf32c(xf1[kt] * xf1[kt]);
        unsigned int q2 = tf32c(xf2[kt] * xf2[kt]), q3 = tf32c(xf3[kt] * xf3[kt]);
        const float2* wr = cl.wI + kt * 256 + lane;
#pragma unroll
        for (int nt = 0; nt < 8; ++nt) {
            float2 w = wr[nt * 32];
            mma_tf32(acc[nt], q0, q1, q2, q3,
                     __float_as_uint(w.x), __float_as_uint(w.y));
        }
    }

    // final epilogue: write s = acc + Tb + Ib
#pragma unroll
    for (int nt = 0; nt < 8; ++nt) {
        int col = nt * 8 + 2 * t4;
        float sbx = cl.Tb[col] + cl.Ib[col];
        float sby = cl.Tb[col + 1] + cl.Ib[col + 1];
        if (r0 < n) *reinterpret_cast<float2*>(cl.s + (size_t)r0 * 64 + col) =
            make_float2(acc[nt][0] + sbx, acc[nt][1] + sby);
        if (r1 < n) *reinterpret_cast<float2*>(cl.s + (size_t)r1 * 64 + col) =
            make_float2(acc[nt][2] + sbx, acc[nt][3] + sby);
    }
}

// ---------------- fused edge scatter (all 5 cells, one launch) ----------------
// 16 lanes per edge, 2 edges per thread, coalesced gathers + red.v4.
__global__ __launch_bounds__(256) void spmm_all(STab tab)
{
    int b = blockIdx.x;
    int c = 0;
#pragma unroll
    for (int i = 1; i < 5; ++i) c += (b >= tab.off[i]);
    const SCell cl = tab.c[c];
    long long t = (long long)(b - tab.off[c]) * 256 + threadIdx.x;
    int l = (int)(t & 15);
    int e0 = (int)(t >> 4) * 2;
    if (e0 >= cl.nnz) return;

    int r0 = __ldg(cl.rows + e0);
    int c0 = __ldg(cl.cols + e0);
    float v0 = __ldg(cl.vals + e0);
    bool has1 = (e0 + 1) < cl.nnz;
    int r1 = r0, c1 = c0;
    float v1 = 0.f;
    if (has1) {
        r1 = __ldg(cl.rows + e0 + 1);
        c1 = __ldg(cl.cols + e0 + 1);
        v1 = __ldg(cl.vals + e0 + 1);
    }
    float4 s0 = *reinterpret_cast<const float4*>(cl.sIn + (size_t)c0 * 64 + l * 4);
    float4 s1 = *reinterpret_cast<const float4*>(cl.sIn + (size_t)c1 * 64 + l * 4);

    float* p0 = ((r0 < cl.nA) ? (cl.outA + (size_t)r0 * 64)
                              : (cl.outB + (size_t)(r0 - cl.nA) * 64)) + l * 4;
    red4(p0, v0 * s0.x, v0 * s0.y, v0 * s0.z, v0 * s0.w);
    if (has1) {
        float* p1 = ((r1 < cl.nA) ? (cl.outA + (size_t)r1 * 64)
                                  : (cl.outB + (size_t)(r1 - cl.nA) * 64)) + l * 4;
        red4(p1, v1 * s1.x, v1 * s1.y, v1 * s1.z, v1 * s1.w);
    }
}

// ---------------- relation attention over R=3 ----------------
__global__ __launch_bounds__(256) void rel_att_kernel(
    const float* __restrict__ z0, const float* __restrict__ z1,
    const float* __restrict__ z2,
    const float* __restrict__ w1, const float* __restrict__ b1,
    const float* __restrict__ w2, float* __restrict__ out, int n)
{
    __shared__ __align__(16) float zb[8][3][64];
    const int lane = threadIdx.x & 31;
    const int wid = threadIdx.x >> 5;

    unsigned long long w1p[32];
#pragma unroll
    for (int m = 0; m < 32; ++m)
        w1p[m] = pk2(w1[(2 * m) * 32 + lane], w1[(2 * m + 1) * 32 + lane]);
    const float b1v = b1[lane];
    const float w2v = w2[lane];

    const int warp0 = blockIdx.x * 8 + wid;
    const int nwarps = gridDim.x * 8;

    for (int node = warp0; node < n; node += nwarps) {
        size_t base = (size_t)node * 64;
        float za0 = z0[base + lane], za1 = z0[base + lane + 32];
        float zc0 = z1[base + lane], zc1 = z1[base + lane + 32];
        float zd0 = z2[base + lane], zd1 = z2[base + lane + 32];
        zb[wid][0][lane] = za0; zb[wid][0][lane + 32] = za1;
        zb[wid][1][lane] = zc0; zb[wid][1][lane + 32] = zc1;
        zb[wid][2][lane] = zd0; zb[wid][2][lane + 32] = zd1;
        __syncwarp();

        float wl[3];
#pragma unroll
        for (int jj = 0; jj < 3; ++jj) {
            const unsigned long long* zp =
                reinterpret_cast<const unsigned long long*>(zb[wid][jj]);
            unsigned long long acc = 0ULL;
#pragma unroll
            for (int m = 0; m < 32; ++m) acc = fma2(zp[m], w1p[m], acc);
            float2 a = up2(acc);
            float cc = tanhf(a.x + a.y + b1v) * w2v;
#pragma unroll
            for (int o = 16; o; o >>= 1) cc += __shfl_xor_sync(0xffffffffu, cc, o);
            wl[jj] = cc;
        }
        float mx = fmaxf(wl[0], fmaxf(wl[1], wl[2]));
        float e0 = __expf(wl[0] - mx), e1 = __expf(wl[1] - mx), e2 = __expf(wl[2] - mx);
        float inv = 1.0f / (e0 + e1 + e2);
        float beta0 = e0 * inv, beta1 = e1 * inv, beta2 = e2 * inv;
        out[base + lane]      = beta0 * za0 + beta1 * zc0 + beta2 * zd0;
        out[base + lane + 32] = beta0 * za1 + beta1 * zc1 + beta2 * zd1;
        __syncwarp();
    }
}

// ---------------- host launcher ----------------
extern "C" void kernel_launch(void* const* d_in, const int* in_sizes, int n_in,
                              void* d_out, int out_size)
{
    const int*   u2i_idx  = (const int*)  d_in[0];
    const float* u2i_val  = (const float*)d_in[1];
    const int*   u2e_idx  = (const int*)  d_in[2];
    const float* u2e_val  = (const float*)d_in[3];
    const int*   i2e_idx  = (const int*)  d_in[4];
    const float* i2e_val  = (const float*)d_in[5];
    const float* u_feat   = (const float*)d_in[6];
    const float* i_feat   = (const float*)d_in[7];
    const float* u2e_feat = (const float*)d_in[8];
    const float* i2e_feat = (const float*)d_in[9];
    const float* Tw_u2i = (const float*)d_in[10];
    const float* Tb_u2i = (const float*)d_in[11];
    const float* Iw_u2i = (const float*)d_in[12];
    const float* Ib_u2i = (const float*)d_in[13];
    const float* Tw_u2e = (const float*)d_in[14];
    const float* Tb_u2e = (const float*)d_in[15];
    const float* Iw_u2e = (const float*)d_in[16];
    const float* Ib_u2e = (const float*)d_in[17];
    const float* Tw_i2e = (const float*)d_in[18];
    const float* Tb_i2e = (const float*)d_in[19];
    const float* Iw_i2e = (const float*)d_in[20];
    const float* Ib_i2e = (const float*)d_in[21];
    const float* uatt_w1 = (const float*)d_in[22];
    const float* uatt_b1 = (const float*)d_in[23];
    const float* uatt_w2 = (const float*)d_in[24];
    const float* iatt_w1 = (const float*)d_in[25];
    const float* iatt_b1 = (const float*)d_in[26];
    const float* iatt_w2 = (const float*)d_in[27];

    const int U = in_sizes[6] / 64;
    const int I = in_sizes[7] / 64;
    const int E = in_sizes[8] / (2 * 64);
    const int NNZ_UI = in_sizes[1];
    const int NNZ_E  = in_sizes[3] / 2;

    float *tu, *ti, *t, *s;
    float2 *wT, *wI;
    cudaGetSymbolAddress((void**)&tu, g_tu);
    cudaGetSymbolAddress((void**)&ti, g_ti);
    cudaGetSymbolAddress((void**)&t,  g_t);
    cudaGetSymbolAddress((void**)&s,  g_s);
    cudaGetSymbolAddress((void**)&wT, g_wT);
    cudaGetSymbolAddress((void**)&wI, g_wI);

    float* outp    = (float*)d_out;
    float* out_u   = outp;
    float* out_i   = outp + (size_t)U * 64;
    float* out_u2e = outp + (size_t)(U + I) * 64;
    float* out_i2e = out_u2e + (size_t)2 * E * 64;

    // pack weight fragments (cells 0,1 = u2e; 2,3 = i2e; 4 = u2i)
    pack_weights<<<40, 256>>>(
        Tw_u2e, Iw_u2e, Tw_u2e + 4096, Iw_u2e + 4096,
        Tw_i2e, Iw_i2e, Tw_i2e + 4096, Iw_i2e + 4096,
        Tw_u2i, Iw_u2i, wT, wI);

    // build GEMM table
    GTab gt;
    {
        int ns[5]    = {U + E, U + E, I + E, I + E, U + I};
        int nAs[5]   = {U, U, I, I, U};
        const float* xAs[5] = {u_feat, u_feat, i_feat, i_feat, u_feat};
        const float* xBs[5] = {u2e_feat, u2e_feat + (size_t)E * 64,
                               i2e_feat, i2e_feat + (size_t)E * 64, i_feat};
        const float* Tbs[5] = {Tb_u2e, Tb_u2e + 64, Tb_i2e, Tb_i2e + 64, Tb_u2i};
        const float* Ibs[5] = {Ib_u2e, Ib_u2e + 64, Ib_i2e, Ib_i2e + 64, Ib_u2i};
        float* outAs[5] = {tu, tu + (size_t)U * 64, ti, ti + (size_t)I * 64, t};
        float* outBs[5] = {out_u2e, out_u2e + (size_t)E * 64,
                           out_i2e, out_i2e + (size_t)E * 64, t + (size_t)U * 64};
        size_t soff = 0;
        gt.off[0] = 0;
        for (int i = 0; i < 5; ++i) {
            gt.c[i].xA = xAs[i]; gt.c[i].xB = xBs[i];
            gt.c[i].nA = nAs[i]; gt.c[i].n = ns[i];
            gt.c[i].wT = wT + (size_t)i * 2048;
            gt.c[i].wI = wI + (size_t)i * 2048;
            gt.c[i].Tb = Tbs[i]; gt.c[i].Ib = Ibs[i];
            gt.c[i].outA = outAs[i]; gt.c[i].outB = outBs[i];
            gt.c[i].s = s + soff * 64;
            soff += (size_t)ns[i];
            gt.off[i + 1] = gt.off[i] + (ns[i] + 63) / 64;
        }
    }
    gcn_gemm_all<<<gt.off[5], 128>>>(gt);

    // build spmm table
    STab st;
    {
        const int* rws[5] = {u2e_idx, u2e_idx + (size_t)2 * NNZ_E,
                             i2e_idx, i2e_idx + (size_t)2 * NNZ_E, u2i_idx};
        const float* vls[5] = {u2e_val, u2e_val + NNZ_E,
                               i2e_val, i2e_val + NNZ_E, u2i_val};
        int nnzs[5] = {NNZ_E, NNZ_E, NNZ_E, NNZ_E, NNZ_UI};
        int nAs[5]  = {U, U, I, I, U + I};
        float* outAs[5] = {tu, tu + (size_t)U * 64, ti, ti + (size_t)I * 64, t};
        float* outBs[5] = {out_u2e, out_u2e + (size_t)E * 64,
                           out_i2e, out_i2e + (size_t)E * 64, t};
        int ns[5] = {U + E, U + E, I + E, I + E, U + I};
        size_t soff = 0;
        st.off[0] = 0;
        for (int i = 0; i < 5; ++i) {
            st.c[i].rows = rws[i];
            st.c[i].cols = rws[i] + nnzs[i];
            st.c[i].vals = vls[i];
            st.c[i].nnz = nnzs[i];
            st.c[i].sIn = s + soff * 64;
            st.c[i].outA = outAs[i];
            st.c[i].nA = nAs[i];
            st.c[i].outB = outBs[i];
            soff += (size_t)ns[i];
            long long th = ((long long)nnzs[i] + 1) / 2 * 16;
            st.off[i + 1] = st.off[i] + (int)((th + 255) / 256);
        }
    }
    spmm_all<<<st.off[5], 256>>>(st);

    // attention
    rel_att_kernel<<<1480, 256>>>(tu, tu + (size_t)U * 64, t,
                                  uatt_w1, uatt_b1, uatt_w2, out_u, U);
    rel_att_kernel<<<1480, 256>>>(ti, ti + (size_t)I * 64, t + (size_t)U * 64,
                                  iatt_w1, iatt_b1, iatt_w2, out_i, I);
}